// round 6
// baseline (speedup 1.0000x reference)
#include <cuda_runtime.h>
#include <cuda_fp16.h>
#include <math.h>
#include <stdint.h>

#define BB 64
#define TT 2048
#define DD 512
#define UU 512

// ---------------- device scratch ----------------
__device__ float g_comb[BB * UU];
__device__ float g_scores[BB * TT];
__device__ float g_spart[2 * BB * TT];
__device__ float g_stats[BB * 2];
__device__ float g_partial[BB * 32 * 4 * DD];
// B fragments (fp16, 2 n8 per uint4): [n4 0..31][k16 0..31][lane 0..31]
__device__ uint4 g_bfrag[32 * 32 * 32];

// ---------------- helpers ----------------
__device__ __forceinline__ uint32_t pack_h2(float x, float y) {
    __half2 h = __floats2half2_rn(x, y);
    return *(uint32_t*)&h;
}

__device__ __forceinline__ void mma_f16(float* d, const uint4& a, uint32_t b0, uint32_t b1) {
    asm volatile(
        "mma.sync.aligned.m16n8k16.row.col.f32.f16.f16.f32 "
        "{%0,%1,%2,%3}, {%4,%5,%6,%7}, {%8,%9}, {%0,%1,%2,%3};"
        : "+f"(d[0]), "+f"(d[1]), "+f"(d[2]), "+f"(d[3])
        : "r"(a.x), "r"(a.y), "r"(a.z), "r"(a.w), "r"(b0), "r"(b1));
}

// ---------------- prep: W1 -> fp16 fragment-major (2 n8 per uint4) ----------------
__global__ void prep_bfrag_kernel(const float* __restrict__ W1) {
    int gidx = blockIdx.x * 256 + threadIdx.x;      // 32768
    int lane = gidx & 31;
    int k16 = (gidx >> 5) & 31;
    int n4 = gidx >> 10;
    int g = lane >> 2, tg = lane & 3;
    int k = k16 * 16 + 2 * tg;
    int ua = (2 * n4) * 8 + g;
    int ub = (2 * n4 + 1) * 8 + g;
    uint4 o;
    o.x = pack_h2(W1[(size_t)k * UU + ua],       W1[(size_t)(k + 1) * UU + ua]);
    o.y = pack_h2(W1[(size_t)(k + 8) * UU + ua], W1[(size_t)(k + 9) * UU + ua]);
    o.z = pack_h2(W1[(size_t)k * UU + ub],       W1[(size_t)(k + 1) * UU + ub]);
    o.w = pack_h2(W1[(size_t)(k + 8) * UU + ub], W1[(size_t)(k + 9) * UU + ub]);
    g_bfrag[gidx] = o;
}

// ---------------- comb[b][u] ----------------
__global__ void comb_kernel(const float* __restrict__ hidden,
                            const float* __restrict__ W2,
                            const float* __restrict__ W1b,
                            const float* __restrict__ W2b) {
    int b = blockIdx.x;
    int u = threadIdx.x;
    __shared__ float h[DD];
    h[u] = hidden[b * DD + u];
    __syncthreads();
    float acc = W1b[u] + W2b[u];
#pragma unroll 8
    for (int d = 0; d < DD; ++d)
        acc = fmaf(h[d], W2[d * UU + u], acc);
    g_comb[b * UU + u] = acc;
}

// ---------------- score GEMM: fused fp32->fp16 A conversion in mainloop ----------------
// grid (2 nchunk, 16 ttile, 64 b), 512 threads = 16 warps (4 warpM x 4 warpN)
// warp tile: 32 t-rows x 64 u-cols; per k16: 16 HMMA, 8 LDG.64 (A fp32) + 4 LDG.128 (B)
__global__ void __launch_bounds__(512)
score_kernel(const float* __restrict__ feat, const float* __restrict__ Vw) {
    __shared__ float comb_s[256];
    __shared__ float v_s[256];
    __shared__ float srow[128];

    int tid = threadIdx.x;
    int wid = tid >> 5, lane = tid & 31;
    int warpM = wid & 3, warpN = wid >> 2;
    int g = lane >> 2, tg = lane & 3;

    int nchunk = blockIdx.x;
    int t0 = blockIdx.y << 7;
    int b = blockIdx.z;
    int u0 = nchunk << 8;

    if (tid < 256) {
        comb_s[tid] = g_comb[b * UU + u0 + tid];
        v_s[tid] = Vw[u0 + tid];
    }
    if (tid < 128) srow[tid] = 0.f;

    // A row pointers (fp32, raw features): rows for mt=0 and mt=1
    const float* rp0 = feat + ((size_t)(b * TT + t0 + warpM * 32 + g)) * DD + 2 * tg;
    const float* rp1 = rp0 + (size_t)16 * DD;
    const uint4* pB = g_bfrag + (((size_t)(nchunk * 16 + warpN * 4) * 32) * 32 + lane);

    float acc[2][8][4];
#pragma unroll
    for (int i = 0; i < 2; ++i)
#pragma unroll
        for (int j = 0; j < 8; ++j)
#pragma unroll
            for (int q = 0; q < 4; ++q) acc[i][j][q] = 0.f;

    // load+convert one A fragment (mt given by row pointer) at k offset
    auto loadA = [&](const float* rp, int koff) -> uint4 {
        float2 f00 = *(const float2*)(rp + koff);
        float2 f10 = *(const float2*)(rp + koff + 8 * DD);
        float2 f01 = *(const float2*)(rp + koff + 8);
        float2 f11 = *(const float2*)(rp + koff + 8 * DD + 8);
        uint4 o;
        o.x = pack_h2(f00.x, f00.y);
        o.y = pack_h2(f10.x, f10.y);
        o.z = pack_h2(f01.x, f01.y);
        o.w = pack_h2(f11.x, f11.y);
        return o;
    };

    uint4 Ab[2][2], Bb[2][4];
    Ab[0][0] = loadA(rp0, 0);
    Ab[0][1] = loadA(rp1, 0);
#pragma unroll
    for (int j = 0; j < 4; ++j) Bb[0][j] = pB[j * 1024];

#pragma unroll 2
    for (int k16 = 0; k16 < 32; ++k16) {
        int cur = k16 & 1, nxt = cur ^ 1;
        if (k16 < 31) {
            int koff = (k16 + 1) * 16;
            Ab[nxt][0] = loadA(rp0, koff);
            Ab[nxt][1] = loadA(rp1, koff);
            int boff = (k16 + 1) * 32;
#pragma unroll
            for (int j = 0; j < 4; ++j) Bb[nxt][j] = pB[j * 1024 + boff];
        }
#pragma unroll
        for (int n4 = 0; n4 < 4; ++n4) {
            uint4 B4 = Bb[cur][n4];
            mma_f16(acc[0][2 * n4],     Ab[cur][0], B4.x, B4.y);
            mma_f16(acc[0][2 * n4 + 1], Ab[cur][0], B4.z, B4.w);
            mma_f16(acc[1][2 * n4],     Ab[cur][1], B4.x, B4.y);
            mma_f16(acc[1][2 * n4 + 1], Ab[cur][1], B4.z, B4.w);
        }
    }

    __syncthreads();

    // ---- epilogue: s = sum_u v[u] * tanh(acc + comb[u]) ----
    float s[4] = {0.f, 0.f, 0.f, 0.f};
#pragma unroll
    for (int nt = 0; nt < 8; ++nt) {
#pragma unroll
        for (int j = 0; j < 2; ++j) {
            int ul = warpN * 64 + nt * 8 + 2 * tg + j;
            float cb = comb_s[ul], vv = v_s[ul];
            s[0] = fmaf(vv, tanhf(acc[0][nt][j] + cb), s[0]);
            s[1] = fmaf(vv, tanhf(acc[0][nt][2 + j] + cb), s[1]);
            s[2] = fmaf(vv, tanhf(acc[1][nt][j] + cb), s[2]);
            s[3] = fmaf(vv, tanhf(acc[1][nt][2 + j] + cb), s[3]);
        }
    }
#pragma unroll
    for (int i = 0; i < 4; ++i) {
        s[i] += __shfl_xor_sync(0xffffffffu, s[i], 1);
        s[i] += __shfl_xor_sync(0xffffffffu, s[i], 2);
    }
    if (tg == 0) {
        int rbase = warpM * 32;
        atomicAdd(&srow[rbase + g], s[0]);
        atomicAdd(&srow[rbase + g + 8], s[1]);
        atomicAdd(&srow[rbase + 16 + g], s[2]);
        atomicAdd(&srow[rbase + 16 + g + 8], s[3]);
    }
    __syncthreads();
    if (tid < 128)
        g_spart[(size_t)nchunk * BB * TT + b * TT + t0 + tid] = srow[tid];
}

// ---------------- softmax stats + score combine ----------------
__global__ void stats_kernel() {
    int b = blockIdx.x;
    int tid = threadIdx.x;   // 256
    __shared__ float red[256];
    float m = -INFINITY;
    for (int t = tid; t < TT; t += 256) {
        float sc = g_spart[b * TT + t] + g_spart[BB * TT + b * TT + t];
        g_scores[b * TT + t] = sc;
        m = fmaxf(m, sc);
    }
    red[tid] = m;
    __syncthreads();
    for (int s = 128; s > 0; s >>= 1) {
        if (tid < s) red[tid] = fmaxf(red[tid], red[tid + s]);
        __syncthreads();
    }
    float mx = red[0];
    __syncthreads();
    float sm = 0.f;
    for (int t = tid; t < TT; t += 256)
        sm += expf(g_scores[b * TT + t] - mx);
    red[tid] = sm;
    __syncthreads();
    for (int s = 128; s > 0; s >>= 1) {
        if (tid < s) red[tid] += red[tid + s];
        __syncthreads();
    }
    if (tid == 0) { g_stats[b * 2] = mx; g_stats[b * 2 + 1] = red[0]; }
}

// ---------------- context partials: 32 splits of 64 t ----------------
__global__ void __launch_bounds__(512)
ctx_partial_kernel(const float* __restrict__ feat) {
    int b = blockIdx.x;
    int s = blockIdx.y;              // 0..31
    int tid = threadIdx.x;           // 512
    __shared__ float w[64];
    float mx = g_stats[b * 2], inv = 1.0f / g_stats[b * 2 + 1];
    int t0 = s * 64;
    if (tid < 64)
        w[tid] = expf(g_scores[b * TT + t0 + tid] - mx) * inv;
    __syncthreads();
    int tl = tid >> 7;               // 0..3
    int dq = (tid & 127) << 2;
    float4 acc = make_float4(0.f, 0.f, 0.f, 0.f);
    const float* fb = feat + ((size_t)b * TT + t0) * DD;
#pragma unroll 4
    for (int i = 0; i < 16; ++i) {
        int t = tl + (i << 2);
        float4 f = *(const float4*)(fb + (size_t)t * DD + dq);
        float ww = w[t];
        acc.x = fmaf(ww, f.x, acc.x);
        acc.y = fmaf(ww, f.y, acc.y);
        acc.z = fmaf(ww, f.z, acc.z);
        acc.w = fmaf(ww, f.w, acc.w);
    }
    *(float4*)(&g_partial[((((size_t)b * 32 + s) * 4) + tl) * DD + dq]) = acc;
}

__global__ void ctx_reduce_kernel(float* __restrict__ out) {
    int b = blockIdx.x;
    int d = threadIdx.x;
    float a = 0.f;
#pragma unroll
    for (int s = 0; s < 128; ++s)
        a += g_partial[((size_t)b * 128 + s) * DD + d];
    out[b * DD + d] = a;
}

// ---------------- launch ----------------
extern "C" void kernel_launch(void* const* d_in, const int* in_sizes, int n_in,
                              void* d_out, int out_size) {
    const float* features = (const float*)d_in[0];
    const float* hidden   = (const float*)d_in[1];
    const float* W1_w     = (const float*)d_in[2];
    const float* W1_b     = (const float*)d_in[3];
    const float* W2_w     = (const float*)d_in[4];
    const float* W2_b     = (const float*)d_in[5];
    const float* V_w      = (const float*)d_in[6];
    // V_b: constant shift, softmax-invariant -> dropped
    float* out = (float*)d_out;

    prep_bfrag_kernel<<<32 * 32 * 32 / 256, 256>>>(W1_w);
    comb_kernel<<<BB, UU>>>(hidden, W2_w, W1_b, W2_b);

    dim3 sgrid(2, 16, BB);
    score_kernel<<<sgrid, 512>>>(features, V_w);

    stats_kernel<<<BB, 256>>>();
    dim3 cgrid(BB, 32);
    ctx_partial_kernel<<<cgrid, 512>>>(features);
    ctx_reduce_kernel<<<BB, DD>>>(out);
}